// round 9
// baseline (speedup 1.0000x reference)
#include <cuda_runtime.h>
#include <cuda_bf16.h>
#include <math.h>

// Problem shape (fixed by the dataset)
#define BB 16
#define NN 1024
#define VV 4096
#define TT 8
#define NG (BB*TT)       // 128 (batch, type) groups
#define KMAX 128         // max group size
#define CHAINCAP 12
#define FULL 0xFFFFFFFFu

// ---------------- device scratch (static; no allocations) ----------------
__device__ int    d_mask_code;          // 0=uint8, 1=int32, 2=float32
__device__ int    d_cnt[NG];
__device__ int    d_idx[NG][KMAX];
__device__ int    d_tok[NG][KMAX];
__device__ float  d_lse[BB*NN];
__device__ double d_val[NG];

// ---------------- helpers ----------------
__device__ __forceinline__ bool mask_at(const void* m, int code, int i) {
    if (code == 0) return ((const unsigned char*)m)[i] != 0;
    if (code == 1) return ((const int*)m)[i] != 0;
    return ((const float*)m)[i] != 0.0f;
}

// order-preserving float -> uint key (monotone), and inverse (exact bit ops)
__device__ __forceinline__ unsigned fkey(float f) {
    unsigned b = __float_as_uint(f);
    return (b & 0x80000000u) ? ~b : (b | 0x80000000u);
}
__device__ __forceinline__ float fkey_inv(unsigned k) {
    unsigned b = (k & 0x80000000u) ? (k ^ 0x80000000u) : ~k;
    return __uint_as_float(b);
}

// ---------------- kernel 1: classify mask dtype layout ----------------
__global__ void detect_mask_kernel(const unsigned char* m) {
    __shared__ int nz[4];
    if (threadIdx.x < 4) nz[threadIdx.x] = 0;
    __syncthreads();
    int local[4] = {0,0,0,0};
    for (int i = threadIdx.x; i < BB*NN; i += blockDim.x)
        if (m[i]) local[i & 3] = 1;
    for (int c = 0; c < 4; c++) if (local[c]) atomicOr(&nz[c], 1);
    __syncthreads();
    if (threadIdx.x == 0) {
        int code;
        if (nz[1])      code = 0;  // bytes at offset%4==1 nonzero -> uint8/bool layout
        else if (nz[0]) code = 1;  // only LSB of each word -> int32 0/1
        else            code = 2;  // pattern of 1.0f (bytes 2,3) -> float32
        d_mask_code = code;
    }
}

// ---------------- kernel 2: build (b,type) groups (ordered, deterministic) ---
__global__ void group_build_kernel(const int* __restrict__ gt,
                                   const int* __restrict__ types,
                                   const void* mask) {
    int g = blockIdx.x;
    int b = g / TT, t = g % TT;
    int lane = threadIdx.x;
    int code = d_mask_code;
    int base = b * NN;
    int cnt = 0;
    for (int p0 = 0; p0 < NN; p0 += 32) {
        int pos = p0 + lane;
        bool pred = (types[base + pos] == t) && mask_at(mask, code, base + pos);
        unsigned bal = __ballot_sync(FULL, pred);
        if (pred) {
            int r = cnt + __popc(bal & ((1u << lane) - 1u));
            if (r < KMAX) {
                d_idx[g][r] = pos;
                d_tok[g][r] = gt[base + pos];
            }
        }
        cnt += __popc(bal);
    }
    if (lane == 0) d_cnt[g] = min(cnt, KMAX);
}

// ---------------- kernel 3: per-masked-row logsumexp (memory-bound bulk) ----
__global__ void lse_kernel(const float* __restrict__ logits, const void* mask) {
    int r = blockIdx.x;                     // 0 .. BB*NN-1
    if (!mask_at(mask, d_mask_code, r)) {
        if (threadIdx.x == 0) d_lse[r] = 0.0f;
        return;
    }
    const float4* row = (const float4*)(logits + (size_t)r * VV);  // 1024 float4
    int t = threadIdx.x;                    // blockDim = 128
    float4 vb[8];
    float mx = -INFINITY;
    #pragma unroll
    for (int q = 0; q < 8; q++) {
        vb[q] = row[t + q * 128];
        mx = fmaxf(mx, fmaxf(fmaxf(vb[q].x, vb[q].y), fmaxf(vb[q].z, vb[q].w)));
    }
    __shared__ float sm[4];
    #pragma unroll
    for (int o = 16; o > 0; o >>= 1) mx = fmaxf(mx, __shfl_xor_sync(FULL, mx, o));
    if ((t & 31) == 0) sm[t >> 5] = mx;
    __syncthreads();
    mx = fmaxf(fmaxf(sm[0], sm[1]), fmaxf(sm[2], sm[3]));
    float s = 0.0f;
    #pragma unroll
    for (int q = 0; q < 8; q++)
        s += __expf(vb[q].x - mx) + __expf(vb[q].y - mx)
           + __expf(vb[q].z - mx) + __expf(vb[q].w - mx);
    __shared__ float ss[4];
    #pragma unroll
    for (int o = 16; o > 0; o >>= 1) s += __shfl_xor_sync(FULL, s, o);
    if ((t & 31) == 0) ss[t >> 5] = s;
    __syncthreads();
    if (t == 0) d_lse[r] = mx + logf(ss[0] + ss[1] + ss[2] + ss[3]);
}

// ---------------- kernel 4: fused gather + full LAPJV solver ----------------
extern __shared__ float cost_sh[];   // KMAX*KMAX floats = 64KB dynamic

// Warp-level LAPJV solver, templated on QMAX = ceil(n/32).
// Columns [n, 32*QMAX) are padded with +INF in cost_sh, so relax/min loops
// need no bounds checks. Exact 2-REDUX min selection throughout.
template<int QMAX>
__device__ void lapjv_solve(int g, int n, int lane,
                            float* u_sh, int* p_sh, int* way_sh, int* x_sh,
                            int* imin_sh, int* freeA, int* freeB, int* nf_shp,
                            int2* pu_sh, float* dset_sh, const float* v_init) {
    float v[QMAX];
    #pragma unroll
    for (int q = 0; q < QMAX; q++) { int j = q * 32 + lane; v[q] = (j < n) ? v_init[j] : 0.0f; }

    // ---- greedy: assign each column to its argmin row if that row is free ----
    if (lane == 0) {
        for (int j = 1; j <= n; j++) {
            int i = imin_sh[j - 1];
            if (x_sh[i] == 0) { x_sh[i] = j; p_sh[j] = i; }
        }
        int nf = 0;
        for (int i = 1; i <= n; i++) if (x_sh[i] == 0) freeA[nf++] = i;
        *nf_shp = nf;
    }
    __syncwarp();
    int nf = *nf_shp;

    // ---- reduction transfer (LAPJV phase 2): tighten duals of assigned rows --
    // Every greedy pair (i, j1) is a column-argmin pair: v[j1] == c[i][j1].
    // mu = min_{j != j1} (c[i][j] - v[j]);  u[i] = mu;  v[j1] = c[i][j1] - mu.
    if (n >= 2) {
        for (int i = 1; i <= n; i++) {
            int j1 = x_sh[i];                  // uniform broadcast read
            if (j1 == 0) continue;
            const float* crow = cost_sh + (size_t)(i - 1) * KMAX;
            unsigned bk = FULL;
            #pragma unroll
            for (int q = 0; q < QMAX; q++) {
                int j = q * 32 + lane + 1;
                unsigned kk = (j == j1) ? FULL : fkey(crow[j - 1] - v[q]);
                bk = min(bk, kk);
            }
            float mu = fkey_inv(__reduce_min_sync(FULL, bk));
            u_sh[i] = mu;                      // uniform all-lane write
            int ol = (j1 - 1) & 31, oq = (j1 - 1) >> 5;
            if (lane == ol) {
                float c1 = crow[j1 - 1];
                #pragma unroll
                for (int q = 0; q < QMAX; q++) if (q == oq) v[q] = c1 - mu;
            }
        }
    }
    __syncwarp();

    // ---- chain-capped augmenting row reduction (exact keys, 3 passes) ----
    int budget = 3 * n;
    for (int pass = 0; pass < 3 && nf > 0 && budget > 0; pass++) {
        int* cur = (pass & 1) ? freeB : freeA;
        int* nxt = (pass & 1) ? freeA : freeB;
        int newnf = 0;
        for (int k = 0; k < nf && budget > 0; k++) {
            int i = cur[k];
            int chain = 0;
            while (i != 0 && budget > 0) {
                budget--; chain++;
                const float* crow = cost_sh + (size_t)(i - 1) * KMAX;
                unsigned kq[QMAX];
                unsigned b1 = FULL; int bj1 = 0x7FFFFFFF;
                #pragma unroll
                for (int q = 0; q < QMAX; q++) {
                    int j = q * 32 + lane + 1;
                    kq[q] = fkey(crow[j - 1] - v[q]);   // padding -> key(+INF), never min
                    if (kq[q] < b1) { b1 = kq[q]; bj1 = j; }
                }
                unsigned k1 = __reduce_min_sync(FULL, b1);
                int j1 = (int)__reduce_min_sync(FULL,
                            (b1 == k1) ? (unsigned)bj1 : 0x7FFFFFFFu);
                // second min (exclude column j1)
                unsigned b2 = FULL; int bj2 = 0x7FFFFFFF;
                #pragma unroll
                for (int q = 0; q < QMAX; q++) {
                    int j = q * 32 + lane + 1;
                    unsigned kk = (j == j1) ? FULL : kq[q];
                    if (kk < b2) { b2 = kk; bj2 = j; }
                }
                unsigned k2 = __reduce_min_sync(FULL, b2);
                int j2 = (int)__reduce_min_sync(FULL,
                            (b2 == k2) ? (unsigned)bj2 : 0x7FFFFFFFu);
                float u1 = fkey_inv(k1), u2 = fkey_inv(k2);
                bool strict = (u1 < u2);

                int jt = j1;
                int i1 = p_sh[jt];              // uniform broadcast read
                if (!strict && i1 != 0) { jt = j2; i1 = p_sh[jt]; }
                if (strict) {
                    int ol = (j1 - 1) & 31, oq = (j1 - 1) >> 5;
                    if (lane == ol) {
                        #pragma unroll
                        for (int q = 0; q < QMAX; q++) if (q == oq) v[q] -= (u2 - u1);
                    }
                }
                // uniform all-lane writes (same value -> benign, self-visible)
                x_sh[i] = jt; p_sh[jt] = i; u_sh[i] = u2;
                if (i1 != 0) x_sh[i1] = 0;
                if (i1 != 0) {
                    if (strict && chain < CHAINCAP) {
                        i = i1;                  // continue chain with displaced row
                    } else {
                        nxt[newnf] = i1; newnf++; i = 0;
                    }
                } else i = 0;
            }
            if (i != 0) { nxt[newnf] = i; newnf++; }   // budget exhausted mid-chain
        }
        __syncwarp();
        nf = newnf;
    }

    // ---- build freelist of remaining free rows + packed pu array ----
    if (lane == 0) {
        int c = 0;
        for (int i = 1; i <= n; i++) if (x_sh[i] == 0) freeA[c++] = i;
        *nf_shp = c;
    }
    for (int j = lane + 1; j <= n; j += 32) {
        int pi = p_sh[j];
        pu_sh[j] = make_int2(pi, pi ? __float_as_int(u_sh[pi]) : 0);
    }
    __syncwarp();
    int nfree = *nf_shp;

    // ---- Dijkstra rounds (absolute-distance, exact 2-REDUX, guard-free) ----
    for (int fi = 0; fi < nfree; fi++) {
        int i = freeA[fi];
        float    dist[QMAX];
        unsigned bkey[QMAX];
        unsigned usedm = 0;
        #pragma unroll
        for (int q = 0; q < QMAX; q++) { dist[q] = INFINITY; bkey[q] = FULL; }

        float D = 0.0f;
        float ui0 = u_sh[i];                    // once per round
        int j0 = 0, i0 = i;
        while (true) {
            const float* crow = cost_sh + (size_t)(i0 - 1) * KMAX;
            float bse = D - ui0;
            float bv[QMAX];
            #pragma unroll
            for (int q = 0; q < QMAX; q++) bv[q] = bse - v[q];
            #pragma unroll
            for (int q = 0; q < QMAX; q++) {
                int j = q * 32 + lane + 1;
                float cur = crow[j - 1] + bv[q];   // padding: +INF, never improves
                if (cur < dist[q]) {               // settled: dist = -INF, never true
                    dist[q] = cur; bkey[q] = fkey(cur); way_sh[j] = j0;
                }
            }
            unsigned bk = bkey[0]; int bq = 0;
            #pragma unroll
            for (int q = 1; q < QMAX; q++) if (bkey[q] < bk) { bk = bkey[q]; bq = q; }
            unsigned kmin = __reduce_min_sync(FULL, bk);
            int jc = (bk == kmin) ? (bq * 32 + lane + 1) : 0x7FFFFFFF;
            int j1 = (int)__reduce_min_sync(FULL, (unsigned)jc);
            D = fkey_inv(kmin);                 // exact settled distance

            int2 pu = pu_sh[j1];                // single LDS.64: row + its u
            j0 = j1;
            if (pu.x == 0) break;               // reached a free column
            dset_sh[j1] = D;                    // uniform all-lane write
            int ol = (j1 - 1) & 31, oq = (j1 - 1) >> 5;
            if (lane == ol) {
                usedm |= (1u << oq);
                #pragma unroll
                for (int q = 0; q < QMAX; q++) if (q == oq) { bkey[q] = FULL; dist[q] = -INFINITY; }
            }
            i0 = pu.x; ui0 = __int_as_float(pu.y);
        }

        // end-of-round potential updates (settled dists from dset_sh)
        if (lane == 0) u_sh[i] += D;
        #pragma unroll
        for (int q = 0; q < QMAX; q++) {
            if ((usedm >> q) & 1u) {
                int j = q * 32 + lane + 1;
                float incr = D - dset_sh[j];
                v[q] -= incr;
                u_sh[p_sh[j]] += incr;          // distinct rows, no conflict
            }
        }
        __syncwarp();                           // publish way_sh/u_sh
        if (lane == 0) {
            p_sh[0] = i;                        // root for augmentation
            int j = j0;
            while (j) { int jp = way_sh[j]; p_sh[j] = p_sh[jp]; j = jp; }
        }
        __syncwarp();                           // publish p_sh
        // rebuild packed pu (u and p changed for used/path columns)
        for (int j = lane + 1; j <= n; j += 32) {
            int pi = p_sh[j];
            pu_sh[j] = make_int2(pi, pi ? __float_as_int(u_sh[pi]) : 0);
        }
        __syncwarp();
    }

    // optimal value = sum_j cost[p[j]-1][j-1]
    double s = 0.0;
    for (int j = lane + 1; j <= n; j += 32) {
        int pi = p_sh[j];
        s += (double)cost_sh[(size_t)(pi - 1) * KMAX + (j - 1)];
    }
    #pragma unroll
    for (int o = 16; o > 0; o >>= 1) s += __shfl_down_sync(FULL, s, o);
    if (lane == 0) d_val[g] = s;
}

__global__ void __launch_bounds__(128, 1) jv_kernel(const float* __restrict__ logits) {
    __shared__ float v_sh[KMAX];
    __shared__ float u_sh[KMAX + 1];
    __shared__ int   p_sh[KMAX + 1];     // col -> row (1-based), 0 = free
    __shared__ int   way_sh[KMAX + 1];
    __shared__ int   x_sh[KMAX + 1];     // row -> col (1-based), 0 = free
    __shared__ int   imin_sh[KMAX];
    __shared__ int   s_idx[KMAX], s_tok[KMAX];
    __shared__ int   freeA[KMAX], freeB[KMAX];
    __shared__ int2  pu_sh[KMAX + 1];
    __shared__ float dset_sh[KMAX + 1];
    __shared__ int   nf_sh;

    int g = blockIdx.x;
    int n = d_cnt[g];
    int tid = threadIdx.x;
    if (n == 0) { if (tid == 0) d_val[g] = 0.0; return; }

    if (tid < n) { s_idx[tid] = d_idx[g][tid]; s_tok[tid] = d_tok[g][tid]; }
    if (tid <= n) { u_sh[tid] = 0.0f; p_sh[tid] = 0; x_sh[tid] = 0; }
    __syncthreads();

    int qmax = (n + 31) >> 5;
    int npad = qmax * 32;

    // gather cost = -logits[b, idx[i], tok[j]] into shared; pad cols with +INF
    const float* base = logits + (size_t)(g / TT) * NN * VV;
    int ntot = n * npad;
    for (int e = tid; e < ntot; e += 128) {
        int i = e / npad, j = e - i * npad;
        cost_sh[i * KMAX + j] = (j < n)
            ? -__ldg(base + (size_t)s_idx[i] * VV + s_tok[j])
            : INFINITY;
    }
    __syncthreads();

    // column reduction: v[j] = min_i c[i][j], remember argmin row (1-based)
    if (tid < n) {
        float mn = cost_sh[tid]; int am = 1;
        for (int i = 1; i < n; i++) {
            float c = cost_sh[i * KMAX + tid];
            if (c < mn) { mn = c; am = i + 1; }
        }
        v_sh[tid] = mn; imin_sh[tid] = am;
    }
    __syncthreads();
    if (tid >= 32) return;                 // warp 0 only from here
    int lane = tid;

    if (qmax == 2)
        lapjv_solve<2>(g, n, lane, u_sh, p_sh, way_sh, x_sh, imin_sh, freeA, freeB, &nf_sh, pu_sh, dset_sh, v_sh);
    else if (qmax == 3)
        lapjv_solve<3>(g, n, lane, u_sh, p_sh, way_sh, x_sh, imin_sh, freeA, freeB, &nf_sh, pu_sh, dset_sh, v_sh);
    else if (qmax <= 1)
        lapjv_solve<1>(g, n, lane, u_sh, p_sh, way_sh, x_sh, imin_sh, freeA, freeB, &nf_sh, pu_sh, dset_sh, v_sh);
    else
        lapjv_solve<4>(g, n, lane, u_sh, p_sh, way_sh, x_sh, imin_sh, freeA, freeB, &nf_sh, pu_sh, dset_sh, v_sh);
}

// ---------------- kernel 5: deterministic final reduction (1024 thr) --------
__global__ void final_kernel(float* out) {
    __shared__ double red[1024];
    __shared__ int    redc[1024];
    int t = threadIdx.x;
    const float4* l4 = (const float4*)d_lse;        // 4096 float4
    double s = 0.0;
    #pragma unroll
    for (int q = 0; q < 4; q++) {
        float4 x = l4[t + q * 1024];
        s += (double)x.x + (double)x.y + (double)x.z + (double)x.w;
    }
    int cnt = 0;
    if (t < NG) { s += d_val[t]; cnt = d_cnt[t]; }
    red[t] = s; redc[t] = cnt;
    __syncthreads();
    for (int o = 512; o > 0; o >>= 1) {
        if (t < o) { red[t] += red[t + o]; redc[t] += redc[t + o]; }
        __syncthreads();
    }
    if (t == 0) out[0] = (float)(red[0] / (double)redc[0]);
}

// ---------------- launcher ----------------
extern "C" void kernel_launch(void* const* d_in, const int* in_sizes, int n_in,
                              void* d_out, int out_size) {
    const float* logits = (const float*)d_in[0];
    const int*   gt     = (const int*)d_in[1];
    const int*   types  = (const int*)d_in[2];
    const void*  mask   = d_in[3];

    cudaFuncSetAttribute(jv_kernel, cudaFuncAttributeMaxDynamicSharedMemorySize,
                         KMAX * KMAX * (int)sizeof(float));

    // one-time side-stream setup (host objects only; no device memory)
    static int have_streams = -1;
    static cudaStream_t s2;
    static cudaEvent_t evF, evJ;
    if (have_streams < 0) {
        int lo = 0, hi = 0;
        cudaDeviceGetStreamPriorityRange(&lo, &hi);   // lo = least priority
        have_streams =
            (cudaStreamCreateWithPriority(&s2, cudaStreamNonBlocking, lo) == cudaSuccess &&
             cudaEventCreateWithFlags(&evF, cudaEventDisableTiming) == cudaSuccess &&
             cudaEventCreateWithFlags(&evJ, cudaEventDisableTiming) == cudaSuccess) ? 1 : 0;
    }

    detect_mask_kernel<<<1, 256>>>((const unsigned char*)mask);

    if (have_streams) {
        cudaEventRecord(evF, 0);                     // after detect (lse dep)
        group_build_kernel<<<NG, 32>>>(gt, types, mask);
        jv_kernel<<<NG, 128, KMAX * KMAX * (int)sizeof(float)>>>(logits);
        // fork lse AFTER jv is enqueued, on a low-priority stream: jv's 128
        // blocks grab their SMs first; lse fills remaining capacity under it.
        cudaStreamWaitEvent(s2, evF, 0);
        lse_kernel<<<BB*NN, 128, 0, s2>>>(logits, mask);
        cudaEventRecord(evJ, s2);
        cudaStreamWaitEvent(0, evJ, 0);              // join before final
    } else {
        lse_kernel<<<BB*NN, 128>>>(logits, mask);
        group_build_kernel<<<NG, 32>>>(gt, types, mask);
        jv_kernel<<<NG, 128, KMAX * KMAX * (int)sizeof(float)>>>(logits);
    }
    final_kernel<<<1, 1024>>>((float*)d_out);
}

// round 10
// speedup vs baseline: 1.2608x; 1.2608x over previous
#include <cuda_runtime.h>
#include <cuda_bf16.h>
#include <math.h>

// Problem shape (fixed by the dataset)
#define BB 16
#define NN 1024
#define VV 4096
#define TT 8
#define NG (BB*TT)       // 128 (batch, type) groups
#define KMAX 128         // max group size
#define CHAINCAP 8
#define FULL 0xFFFFFFFFu

// ---------------- device scratch (static; no allocations) ----------------
__device__ int    d_mask_code;          // 0=uint8, 1=int32, 2=float32
__device__ int    d_cnt[NG];
__device__ int    d_idx[NG][KMAX];
__device__ int    d_tok[NG][KMAX];
__device__ float  d_lse[BB*NN];
__device__ double d_val[NG];

// ---------------- helpers ----------------
__device__ __forceinline__ bool mask_at(const void* m, int code, int i) {
    if (code == 0) return ((const unsigned char*)m)[i] != 0;
    if (code == 1) return ((const int*)m)[i] != 0;
    return ((const float*)m)[i] != 0.0f;
}

// order-preserving float -> uint key (monotone), and inverse (exact bit ops)
__device__ __forceinline__ unsigned fkey(float f) {
    unsigned b = __float_as_uint(f);
    return (b & 0x80000000u) ? ~b : (b | 0x80000000u);
}
__device__ __forceinline__ float fkey_inv(unsigned k) {
    unsigned b = (k & 0x80000000u) ? (k ^ 0x80000000u) : ~k;
    return __uint_as_float(b);
}

// ---------------- kernel 1: classify mask dtype layout ----------------
__global__ void detect_mask_kernel(const unsigned char* m) {
    __shared__ int nz[4];
    if (threadIdx.x < 4) nz[threadIdx.x] = 0;
    __syncthreads();
    int local[4] = {0,0,0,0};
    for (int i = threadIdx.x; i < BB*NN; i += blockDim.x)
        if (m[i]) local[i & 3] = 1;
    for (int c = 0; c < 4; c++) if (local[c]) atomicOr(&nz[c], 1);
    __syncthreads();
    if (threadIdx.x == 0) {
        int code;
        if (nz[1])      code = 0;  // bytes at offset%4==1 nonzero -> uint8/bool layout
        else if (nz[0]) code = 1;  // only LSB of each word -> int32 0/1
        else            code = 2;  // pattern of 1.0f (bytes 2,3) -> float32
        d_mask_code = code;
    }
}

// ---------------- kernel 2: build (b,type) groups (ordered, deterministic) ---
__global__ void group_build_kernel(const int* __restrict__ gt,
                                   const int* __restrict__ types,
                                   const void* mask) {
    int g = blockIdx.x;
    int b = g / TT, t = g % TT;
    int lane = threadIdx.x;
    int code = d_mask_code;
    int base = b * NN;
    int cnt = 0;
    for (int p0 = 0; p0 < NN; p0 += 32) {
        int pos = p0 + lane;
        bool pred = (types[base + pos] == t) && mask_at(mask, code, base + pos);
        unsigned bal = __ballot_sync(FULL, pred);
        if (pred) {
            int r = cnt + __popc(bal & ((1u << lane) - 1u));
            if (r < KMAX) {
                d_idx[g][r] = pos;
                d_tok[g][r] = gt[base + pos];
            }
        }
        cnt += __popc(bal);
    }
    if (lane == 0) d_cnt[g] = min(cnt, KMAX);
}

// ---------------- kernel 3: per-masked-row logsumexp (memory-bound bulk) ----
__global__ void lse_kernel(const float* __restrict__ logits, const void* mask) {
    int r = blockIdx.x;                     // 0 .. BB*NN-1
    if (!mask_at(mask, d_mask_code, r)) {
        if (threadIdx.x == 0) d_lse[r] = 0.0f;
        return;
    }
    const float4* row = (const float4*)(logits + (size_t)r * VV);  // 1024 float4
    int t = threadIdx.x;                    // blockDim = 128
    float4 vb[8];
    float mx = -INFINITY;
    #pragma unroll
    for (int q = 0; q < 8; q++) {
        vb[q] = row[t + q * 128];
        mx = fmaxf(mx, fmaxf(fmaxf(vb[q].x, vb[q].y), fmaxf(vb[q].z, vb[q].w)));
    }
    __shared__ float sm[4];
    #pragma unroll
    for (int o = 16; o > 0; o >>= 1) mx = fmaxf(mx, __shfl_xor_sync(FULL, mx, o));
    if ((t & 31) == 0) sm[t >> 5] = mx;
    __syncthreads();
    mx = fmaxf(fmaxf(sm[0], sm[1]), fmaxf(sm[2], sm[3]));
    float s = 0.0f;
    #pragma unroll
    for (int q = 0; q < 8; q++)
        s += __expf(vb[q].x - mx) + __expf(vb[q].y - mx)
           + __expf(vb[q].z - mx) + __expf(vb[q].w - mx);
    __shared__ float ss[4];
    #pragma unroll
    for (int o = 16; o > 0; o >>= 1) s += __shfl_xor_sync(FULL, s, o);
    if ((t & 31) == 0) ss[t >> 5] = s;
    __syncthreads();
    if (t == 0) d_lse[r] = mx + logf(ss[0] + ss[1] + ss[2] + ss[3]);
}

// ---------------- kernel 4: fused gather + LAPJV solver ---------------------
extern __shared__ float cost_sh[];   // KMAX*KMAX floats = 64KB dynamic

// Warp-level LAPJV solver, templated on QMAX = ceil(n/32).
// Exact 2-REDUX ARR; Dijkstra uses REDUX min + ballot argmin with speculative
// pu load (selected column always a true min -> monotonicity preserved).
template<int QMAX>
__device__ void lapjv_solve(int g, int n, int lane,
                            float* u_sh, int* p_sh, int* way_sh, int* x_sh,
                            int* imin_sh, int* freeA, int* freeB, int* nf_shp,
                            int2* pu_sh, const float* v_init) {
    float v[QMAX];
    #pragma unroll
    for (int q = 0; q < QMAX; q++) { int j = q * 32 + lane; v[q] = (j < n) ? v_init[j] : 0.0f; }

    // greedy: assign each column to its argmin row if that row is still free
    if (lane == 0) {
        for (int j = 1; j <= n; j++) {
            int i = imin_sh[j - 1];
            if (x_sh[i] == 0) { x_sh[i] = j; p_sh[j] = i; }
        }
        int nf = 0;
        for (int i = 1; i <= n; i++) if (x_sh[i] == 0) freeA[nf++] = i;
        *nf_shp = nf;
    }
    __syncwarp();
    int nf = *nf_shp;

    // ---- chain-capped augmenting row reduction (exact keys, 2 passes) ----
    // All shared updates inside are warp-uniform values written by ALL lanes.
    int budget = 2 * n + 32;
    for (int pass = 0; pass < 2 && nf > 0 && budget > 0; pass++) {
        int* cur = (pass == 0) ? freeA : freeB;
        int* nxt = (pass == 0) ? freeB : freeA;
        int newnf = 0;
        for (int k = 0; k < nf && budget > 0; k++) {
            int i = cur[k];
            int chain = 0;
            while (i != 0 && budget > 0) {
                budget--; chain++;
                const float* crow = cost_sh + (size_t)(i - 1) * KMAX;
                unsigned kq[QMAX];
                unsigned b1 = FULL; int bj1 = 0x7FFFFFFF;
                #pragma unroll
                for (int q = 0; q < QMAX; q++) {
                    int j = q * 32 + lane + 1;
                    if (j <= n) {
                        kq[q] = fkey(crow[j - 1] - v[q]);
                        if (kq[q] < b1) { b1 = kq[q]; bj1 = j; }
                    } else kq[q] = FULL;
                }
                unsigned k1 = __reduce_min_sync(FULL, b1);
                int j1 = (int)__reduce_min_sync(FULL,
                            (b1 == k1) ? (unsigned)bj1 : 0x7FFFFFFFu);
                // second min (exclude column j1)
                unsigned b2 = FULL; int bj2 = 0x7FFFFFFF;
                #pragma unroll
                for (int q = 0; q < QMAX; q++) {
                    int j = q * 32 + lane + 1;
                    unsigned kk = (j == j1) ? FULL : kq[q];
                    if (kk < b2) { b2 = kk; bj2 = j; }
                }
                unsigned k2 = __reduce_min_sync(FULL, b2);
                int j2 = (int)__reduce_min_sync(FULL,
                            (b2 == k2) ? (unsigned)bj2 : 0x7FFFFFFFu);
                float u1 = fkey_inv(k1), u2 = fkey_inv(k2);
                bool strict = (u1 < u2);

                int jt = j1;
                int i1 = p_sh[jt];              // uniform broadcast read
                if (!strict && i1 != 0) { jt = j2; i1 = p_sh[jt]; }
                if (strict) {
                    int ol = (j1 - 1) & 31, oq = (j1 - 1) >> 5;
                    if (lane == ol) {
                        #pragma unroll
                        for (int q = 0; q < QMAX; q++) if (q == oq) v[q] -= (u2 - u1);
                    }
                }
                // uniform all-lane writes (same value -> benign, self-visible)
                x_sh[i] = jt; p_sh[jt] = i; u_sh[i] = u2;
                if (i1 != 0) x_sh[i1] = 0;
                if (i1 != 0) {
                    if (strict && chain < CHAINCAP) {
                        i = i1;                  // continue chain with displaced row
                    } else {
                        nxt[newnf] = i1; newnf++; i = 0;
                    }
                } else i = 0;
            }
            if (i != 0) { nxt[newnf] = i; newnf++; }   // budget exhausted mid-chain
        }
        __syncwarp();
        nf = newnf;
    }

    // ---- build freelist of remaining free rows + packed pu array ----
    // pu_sh[j] = { (p[j]-1)*KMAX  (row base offset, or -1 if free), bits(u[p[j]]) }
    if (lane == 0) {
        int c = 0;
        for (int i = 1; i <= n; i++) if (x_sh[i] == 0) freeA[c++] = i;
        *nf_shp = c;
    }
    for (int j = lane + 1; j <= n; j += 32) {
        int pi = p_sh[j];
        pu_sh[j] = make_int2(pi ? (pi - 1) * KMAX : -1,
                             pi ? __float_as_int(u_sh[pi]) : 0);
    }
    __syncwarp();
    int nfree = *nf_shp;

    // ---- Dijkstra rounds (absolute-distance, REDUX min + ballot argmin) ----
    for (int fi = 0; fi < nfree; fi++) {
        int i = freeA[fi];
        float    dist[QMAX];
        unsigned bkey[QMAX];
        unsigned usedm = 0;
        #pragma unroll
        for (int q = 0; q < QMAX; q++) { dist[q] = INFINITY; bkey[q] = FULL; }

        float D = 0.0f;
        float ui0 = u_sh[i];                    // once per round
        int roff = (i - 1) * KMAX;              // row base offset of current tree row
        int j0 = 0;
        while (true) {
            const float* crow = cost_sh + roff;
            float bse = D - ui0;
            #pragma unroll
            for (int q = 0; q < QMAX; q++) {
                int j = q * 32 + lane + 1;
                if (j <= n && !((usedm >> q) & 1u)) {
                    float cur = crow[j - 1] + (bse - v[q]);
                    if (cur < dist[q]) { dist[q] = cur; bkey[q] = fkey(cur); way_sh[j] = j0; }
                }
            }
            unsigned bk = bkey[0]; int bq = 0;
            #pragma unroll
            for (int q = 1; q < QMAX; q++) if (bkey[q] < bk) { bk = bkey[q]; bq = q; }
            int bj = bq * 32 + lane + 1;        // this lane's argmin column
            unsigned kmin = __reduce_min_sync(FULL, bk);
            bool own = (bk == kmin);
            unsigned mball = __ballot_sync(FULL, own);
            int src = __ffs((int)mball) - 1;    // lowest owner lane (a true min)
            int2 myu = make_int2(0, 0);
            if (own) myu = pu_sh[bj];           // speculative load, overlaps ballot/ffs
            int j1  = __shfl_sync(FULL, bj, src);
            int off = __shfl_sync(FULL, myu.x, src);
            int ub  = __shfl_sync(FULL, myu.y, src);
            D = fkey_inv(kmin);                 // exact settled distance

            j0 = j1;
            if (off < 0) break;                 // reached a free column
            int ol = (j1 - 1) & 31, oq = (j1 - 1) >> 5;
            if (lane == ol) {
                usedm |= (1u << oq);
                #pragma unroll
                for (int q = 0; q < QMAX; q++) if (q == oq) bkey[q] = FULL;
            }
            roff = off; ui0 = __int_as_float(ub);
        }

        // end-of-round potential updates
        if (lane == 0) u_sh[i] += D;
        #pragma unroll
        for (int q = 0; q < QMAX; q++) {
            if ((usedm >> q) & 1u) {
                int j = q * 32 + lane + 1;
                float incr = D - dist[q];
                v[q] -= incr;
                u_sh[p_sh[j]] += incr;          // distinct rows, no conflict
            }
        }
        __syncwarp();                           // publish way_sh/u_sh
        if (lane == 0) {
            p_sh[0] = i;                        // root for augmentation
            int j = j0;
            while (j) { int jp = way_sh[j]; p_sh[j] = p_sh[jp]; j = jp; }
        }
        __syncwarp();                           // publish p_sh
        // rebuild packed pu (u and p changed for used/path columns)
        for (int j = lane + 1; j <= n; j += 32) {
            int pi = p_sh[j];
            pu_sh[j] = make_int2(pi ? (pi - 1) * KMAX : -1,
                                 pi ? __float_as_int(u_sh[pi]) : 0);
        }
        __syncwarp();
    }

    // optimal value = sum_j cost[p[j]-1][j-1]
    double s = 0.0;
    for (int j = lane + 1; j <= n; j += 32) {
        int pi = p_sh[j];
        s += (double)cost_sh[(size_t)(pi - 1) * KMAX + (j - 1)];
    }
    #pragma unroll
    for (int o = 16; o > 0; o >>= 1) s += __shfl_down_sync(FULL, s, o);
    if (lane == 0) d_val[g] = s;
}

__global__ void __launch_bounds__(128, 1) jv_kernel(const float* __restrict__ logits) {
    __shared__ float v_sh[KMAX];
    __shared__ float u_sh[KMAX + 1];
    __shared__ int   p_sh[KMAX + 1];     // col -> row (1-based), 0 = free
    __shared__ int   way_sh[KMAX + 1];
    __shared__ int   x_sh[KMAX + 1];     // row -> col (1-based), 0 = free
    __shared__ int   imin_sh[KMAX];
    __shared__ int   s_idx[KMAX], s_tok[KMAX];
    __shared__ int   freeA[KMAX], freeB[KMAX];
    __shared__ int2  pu_sh[KMAX + 1];
    __shared__ int   nf_sh;

    int g = blockIdx.x;
    int n = d_cnt[g];
    int tid = threadIdx.x;
    if (n == 0) { if (tid == 0) d_val[g] = 0.0; return; }

    if (tid < n) { s_idx[tid] = d_idx[g][tid]; s_tok[tid] = d_tok[g][tid]; }
    if (tid <= n) { u_sh[tid] = 0.0f; p_sh[tid] = 0; x_sh[tid] = 0; }
    __syncthreads();

    // gather cost = -logits[b, idx[i], tok[j]] directly into shared
    const float* base = logits + (size_t)(g / TT) * NN * VV;
    int nn = n * n;
    for (int e = tid; e < nn; e += 128) {
        int i = e / n, j = e - i * n;
        cost_sh[i * KMAX + j] = -__ldg(base + (size_t)s_idx[i] * VV + s_tok[j]);
    }
    __syncthreads();

    // column reduction: v[j] = min_i c[i][j], remember argmin row (1-based)
    if (tid < n) {
        float mn = cost_sh[tid]; int am = 1;
        for (int i = 1; i < n; i++) {
            float c = cost_sh[i * KMAX + tid];
            if (c < mn) { mn = c; am = i + 1; }
        }
        v_sh[tid] = mn; imin_sh[tid] = am;
    }
    __syncthreads();
    if (tid >= 32) return;                 // warp 0 only from here
    int lane = tid;

    int qmax = (n + 31) >> 5;
    if (qmax == 2)
        lapjv_solve<2>(g, n, lane, u_sh, p_sh, way_sh, x_sh, imin_sh, freeA, freeB, &nf_sh, pu_sh, v_sh);
    else if (qmax == 3)
        lapjv_solve<3>(g, n, lane, u_sh, p_sh, way_sh, x_sh, imin_sh, freeA, freeB, &nf_sh, pu_sh, v_sh);
    else if (qmax <= 1)
        lapjv_solve<1>(g, n, lane, u_sh, p_sh, way_sh, x_sh, imin_sh, freeA, freeB, &nf_sh, pu_sh, v_sh);
    else
        lapjv_solve<4>(g, n, lane, u_sh, p_sh, way_sh, x_sh, imin_sh, freeA, freeB, &nf_sh, pu_sh, v_sh);
}

// ---------------- kernel 5: deterministic final reduction (1024 thr) --------
__global__ void final_kernel(float* out) {
    __shared__ double red[1024];
    __shared__ int    redc[1024];
    int t = threadIdx.x;
    const float4* l4 = (const float4*)d_lse;        // 4096 float4
    double s = 0.0;
    #pragma unroll
    for (int q = 0; q < 4; q++) {
        float4 x = l4[t + q * 1024];
        s += (double)x.x + (double)x.y + (double)x.z + (double)x.w;
    }
    int cnt = 0;
    if (t < NG) { s += d_val[t]; cnt = d_cnt[t]; }
    red[t] = s; redc[t] = cnt;
    __syncthreads();
    for (int o = 512; o > 0; o >>= 1) {
        if (t < o) { red[t] += red[t + o]; redc[t] += redc[t + o]; }
        __syncthreads();
    }
    if (t == 0) out[0] = (float)(red[0] / (double)redc[0]);
}

// ---------------- launcher ----------------
extern "C" void kernel_launch(void* const* d_in, const int* in_sizes, int n_in,
                              void* d_out, int out_size) {
    const float* logits = (const float*)d_in[0];
    const int*   gt     = (const int*)d_in[1];
    const int*   types  = (const int*)d_in[2];
    const void*  mask   = d_in[3];

    cudaFuncSetAttribute(jv_kernel, cudaFuncAttributeMaxDynamicSharedMemorySize,
                         KMAX * KMAX * (int)sizeof(float));

    // one-time side-stream setup (host objects only; no device memory)
    static int have_streams = -1;
    static cudaStream_t s2;
    static cudaEvent_t evF, evJ;
    if (have_streams < 0) {
        int lo = 0, hi = 0;
        cudaDeviceGetStreamPriorityRange(&lo, &hi);   // lo = least priority
        have_streams =
            (cudaStreamCreateWithPriority(&s2, cudaStreamNonBlocking, lo) == cudaSuccess &&
             cudaEventCreateWithFlags(&evF, cudaEventDisableTiming) == cudaSuccess &&
             cudaEventCreateWithFlags(&evJ, cudaEventDisableTiming) == cudaSuccess) ? 1 : 0;
    }

    detect_mask_kernel<<<1, 256>>>((const unsigned char*)mask);

    if (have_streams) {
        cudaEventRecord(evF, 0);                     // after detect (lse dep)
        group_build_kernel<<<NG, 32>>>(gt, types, mask);
        jv_kernel<<<NG, 128, KMAX * KMAX * (int)sizeof(float)>>>(logits);
        // fork lse AFTER jv is enqueued, on a low-priority stream: jv's 128
        // blocks grab their SMs first; lse fills remaining capacity under it.
        cudaStreamWaitEvent(s2, evF, 0);
        lse_kernel<<<BB*NN, 128, 0, s2>>>(logits, mask);
        cudaEventRecord(evJ, s2);
        cudaStreamWaitEvent(0, evJ, 0);              // join before final
    } else {
        lse_kernel<<<BB*NN, 128>>>(logits, mask);
        group_build_kernel<<<NG, 32>>>(gt, types, mask);
        jv_kernel<<<NG, 128, KMAX * KMAX * (int)sizeof(float)>>>(logits);
    }
    final_kernel<<<1, 1024>>>((float*)d_out);
}

// round 11
// speedup vs baseline: 1.3039x; 1.0342x over previous
#include <cuda_runtime.h>
#include <cuda_bf16.h>
#include <math.h>

// Problem shape (fixed by the dataset)
#define BB 16
#define NN 1024
#define VV 4096
#define TT 8
#define NG (BB*TT)       // 128 (batch, type) groups
#define KMAX 128         // max group size
#define CHAINCAP 8
#define FULL 0xFFFFFFFFu

// ---------------- device scratch (static; no allocations) ----------------
__device__ int    d_mask_code;          // 0=uint8, 1=int32, 2=float32
__device__ int    d_cnt[NG];
__device__ float  d_lse[BB*NN];
__device__ double d_val[NG];

// ---------------- helpers ----------------
__device__ __forceinline__ bool mask_at(const void* m, int code, int i) {
    if (code == 0) return ((const unsigned char*)m)[i] != 0;
    if (code == 1) return ((const int*)m)[i] != 0;
    return ((const float*)m)[i] != 0.0f;
}

// order-preserving float -> uint key (monotone), and inverse (exact bit ops)
__device__ __forceinline__ unsigned fkey(float f) {
    unsigned b = __float_as_uint(f);
    return (b & 0x80000000u) ? ~b : (b | 0x80000000u);
}
__device__ __forceinline__ float fkey_inv(unsigned k) {
    unsigned b = (k & 0x80000000u) ? (k ^ 0x80000000u) : ~k;
    return __uint_as_float(b);
}

// ---------------- kernel 1: classify mask dtype layout ----------------
__global__ void detect_mask_kernel(const unsigned char* m) {
    __shared__ int nz[4];
    if (threadIdx.x < 4) nz[threadIdx.x] = 0;
    __syncthreads();
    int local[4] = {0,0,0,0};
    for (int i = threadIdx.x; i < BB*NN; i += blockDim.x)
        if (m[i]) local[i & 3] = 1;
    for (int c = 0; c < 4; c++) if (local[c]) atomicOr(&nz[c], 1);
    __syncthreads();
    if (threadIdx.x == 0) {
        int code;
        if (nz[1])      code = 0;  // bytes at offset%4==1 nonzero -> uint8/bool layout
        else if (nz[0]) code = 1;  // only LSB of each word -> int32 0/1
        else            code = 2;  // pattern of 1.0f (bytes 2,3) -> float32
        d_mask_code = code;
    }
}

// ---------------- kernel 2: per-masked-row logsumexp (memory-bound bulk) ----
__global__ void lse_kernel(const float* __restrict__ logits, const void* mask) {
    int r = blockIdx.x;                     // 0 .. BB*NN-1
    if (!mask_at(mask, d_mask_code, r)) {
        if (threadIdx.x == 0) d_lse[r] = 0.0f;
        return;
    }
    const float4* row = (const float4*)(logits + (size_t)r * VV);  // 1024 float4
    int t = threadIdx.x;                    // blockDim = 128
    float4 vb[8];
    float mx = -INFINITY;
    #pragma unroll
    for (int q = 0; q < 8; q++) {
        vb[q] = row[t + q * 128];
        mx = fmaxf(mx, fmaxf(fmaxf(vb[q].x, vb[q].y), fmaxf(vb[q].z, vb[q].w)));
    }
    __shared__ float sm[4];
    #pragma unroll
    for (int o = 16; o > 0; o >>= 1) mx = fmaxf(mx, __shfl_xor_sync(FULL, mx, o));
    if ((t & 31) == 0) sm[t >> 5] = mx;
    __syncthreads();
    mx = fmaxf(fmaxf(sm[0], sm[1]), fmaxf(sm[2], sm[3]));
    float s = 0.0f;
    #pragma unroll
    for (int q = 0; q < 8; q++)
        s += __expf(vb[q].x - mx) + __expf(vb[q].y - mx)
           + __expf(vb[q].z - mx) + __expf(vb[q].w - mx);
    __shared__ float ss[4];
    #pragma unroll
    for (int o = 16; o > 0; o >>= 1) s += __shfl_xor_sync(FULL, s, o);
    if ((t & 31) == 0) ss[t >> 5] = s;
    __syncthreads();
    if (t == 0) d_lse[r] = mx + logf(ss[0] + ss[1] + ss[2] + ss[3]);
}

// ------- kernel 3: fused group-build + gather + LAPJV solver (R8 solver) ----
extern __shared__ float cost_sh[];   // KMAX*KMAX floats = 64KB dynamic

// Warp-level LAPJV solver, templated on QMAX = ceil(n/32).
// Exact 2-REDUX min selection; packed (p,u) int2 shared array on the chain.
template<int QMAX>
__device__ void lapjv_solve(int g, int n, int lane,
                            float* u_sh, int* p_sh, int* way_sh, int* x_sh,
                            int* imin_sh, int* freeA, int* freeB, int* nf_shp,
                            int2* pu_sh, const float* v_init) {
    float v[QMAX];
    #pragma unroll
    for (int q = 0; q < QMAX; q++) { int j = q * 32 + lane; v[q] = (j < n) ? v_init[j] : 0.0f; }

    // greedy: assign each column to its argmin row if that row is still free
    if (lane == 0) {
        for (int j = 1; j <= n; j++) {
            int i = imin_sh[j - 1];
            if (x_sh[i] == 0) { x_sh[i] = j; p_sh[j] = i; }
        }
        int nf = 0;
        for (int i = 1; i <= n; i++) if (x_sh[i] == 0) freeA[nf++] = i;
        *nf_shp = nf;
    }
    __syncwarp();
    int nf = *nf_shp;

    // ---- chain-capped augmenting row reduction (exact keys, 2 passes) ----
    // All shared updates inside are warp-uniform values written by ALL lanes.
    int budget = 2 * n + 32;
    for (int pass = 0; pass < 2 && nf > 0 && budget > 0; pass++) {
        int* cur = (pass == 0) ? freeA : freeB;
        int* nxt = (pass == 0) ? freeB : freeA;
        int newnf = 0;
        for (int k = 0; k < nf && budget > 0; k++) {
            int i = cur[k];
            int chain = 0;
            while (i != 0 && budget > 0) {
                budget--; chain++;
                const float* crow = cost_sh + (size_t)(i - 1) * KMAX;
                unsigned kq[QMAX];
                unsigned b1 = FULL; int bj1 = 0x7FFFFFFF;
                #pragma unroll
                for (int q = 0; q < QMAX; q++) {
                    int j = q * 32 + lane + 1;
                    if (j <= n) {
                        kq[q] = fkey(crow[j - 1] - v[q]);
                        if (kq[q] < b1) { b1 = kq[q]; bj1 = j; }
                    } else kq[q] = FULL;
                }
                unsigned k1 = __reduce_min_sync(FULL, b1);
                int j1 = (int)__reduce_min_sync(FULL,
                            (b1 == k1) ? (unsigned)bj1 : 0x7FFFFFFFu);
                // second min (exclude column j1)
                unsigned b2 = FULL; int bj2 = 0x7FFFFFFF;
                #pragma unroll
                for (int q = 0; q < QMAX; q++) {
                    int j = q * 32 + lane + 1;
                    unsigned kk = (j == j1) ? FULL : kq[q];
                    if (kk < b2) { b2 = kk; bj2 = j; }
                }
                unsigned k2 = __reduce_min_sync(FULL, b2);
                int j2 = (int)__reduce_min_sync(FULL,
                            (b2 == k2) ? (unsigned)bj2 : 0x7FFFFFFFu);
                float u1 = fkey_inv(k1), u2 = fkey_inv(k2);
                bool strict = (u1 < u2);

                int jt = j1;
                int i1 = p_sh[jt];              // uniform broadcast read
                if (!strict && i1 != 0) { jt = j2; i1 = p_sh[jt]; }
                if (strict) {
                    int ol = (j1 - 1) & 31, oq = (j1 - 1) >> 5;
                    if (lane == ol) {
                        #pragma unroll
                        for (int q = 0; q < QMAX; q++) if (q == oq) v[q] -= (u2 - u1);
                    }
                }
                // uniform all-lane writes (same value -> benign, self-visible)
                x_sh[i] = jt; p_sh[jt] = i; u_sh[i] = u2;
                if (i1 != 0) x_sh[i1] = 0;
                if (i1 != 0) {
                    if (strict && chain < CHAINCAP) {
                        i = i1;                  // continue chain with displaced row
                    } else {
                        nxt[newnf] = i1; newnf++; i = 0;
                    }
                } else i = 0;
            }
            if (i != 0) { nxt[newnf] = i; newnf++; }   // budget exhausted mid-chain
        }
        __syncwarp();
        nf = newnf;
    }

    // ---- build freelist of remaining free rows + packed pu array ----
    if (lane == 0) {
        int c = 0;
        for (int i = 1; i <= n; i++) if (x_sh[i] == 0) freeA[c++] = i;
        *nf_shp = c;
    }
    for (int j = lane + 1; j <= n; j += 32) {
        int pi = p_sh[j];
        pu_sh[j] = make_int2(pi, pi ? __float_as_int(u_sh[pi]) : 0);
    }
    __syncwarp();
    int nfree = *nf_shp;

    // ---- Dijkstra rounds (absolute-distance, exact 2-REDUX, pu-packed) ----
    for (int fi = 0; fi < nfree; fi++) {
        int i = freeA[fi];
        float    dist[QMAX];
        unsigned bkey[QMAX];
        unsigned usedm = 0;
        #pragma unroll
        for (int q = 0; q < QMAX; q++) { dist[q] = INFINITY; bkey[q] = FULL; }

        float D = 0.0f;
        float ui0 = u_sh[i];                    // once per round
        int j0 = 0, i0 = i;
        while (true) {
            const float* crow = cost_sh + (size_t)(i0 - 1) * KMAX;
            float bse = D - ui0;
            #pragma unroll
            for (int q = 0; q < QMAX; q++) {
                int j = q * 32 + lane + 1;
                if (j <= n && !((usedm >> q) & 1u)) {
                    float cur = crow[j - 1] + (bse - v[q]);
                    if (cur < dist[q]) { dist[q] = cur; bkey[q] = fkey(cur); way_sh[j] = j0; }
                }
            }
            unsigned bk = bkey[0]; int bq = 0;
            #pragma unroll
            for (int q = 1; q < QMAX; q++) if (bkey[q] < bk) { bk = bkey[q]; bq = q; }
            unsigned kmin = __reduce_min_sync(FULL, bk);
            int jc = (bk == kmin) ? (bq * 32 + lane + 1) : 0x7FFFFFFF;
            int j1 = (int)__reduce_min_sync(FULL, (unsigned)jc);
            D = fkey_inv(kmin);                 // exact settled distance

            int2 pu = pu_sh[j1];                // single LDS.64: row + its u
            j0 = j1;
            if (pu.x == 0) break;               // reached a free column
            int ol = (j1 - 1) & 31, oq = (j1 - 1) >> 5;
            if (lane == ol) {
                usedm |= (1u << oq);
                #pragma unroll
                for (int q = 0; q < QMAX; q++) if (q == oq) bkey[q] = FULL;
            }
            i0 = pu.x; ui0 = __int_as_float(pu.y);
        }

        // end-of-round potential updates
        if (lane == 0) u_sh[i] += D;
        #pragma unroll
        for (int q = 0; q < QMAX; q++) {
            if ((usedm >> q) & 1u) {
                int j = q * 32 + lane + 1;
                float incr = D - dist[q];
                v[q] -= incr;
                u_sh[p_sh[j]] += incr;          // distinct rows, no conflict
            }
        }
        __syncwarp();                           // publish way_sh/u_sh
        if (lane == 0) {
            p_sh[0] = i;                        // root for augmentation
            int j = j0;
            while (j) { int jp = way_sh[j]; p_sh[j] = p_sh[jp]; j = jp; }
        }
        __syncwarp();                           // publish p_sh
        // rebuild packed pu (u and p changed for used/path columns)
        for (int j = lane + 1; j <= n; j += 32) {
            int pi = p_sh[j];
            pu_sh[j] = make_int2(pi, pi ? __float_as_int(u_sh[pi]) : 0);
        }
        __syncwarp();
    }

    // optimal value = sum_j cost[p[j]-1][j-1]
    double s = 0.0;
    for (int j = lane + 1; j <= n; j += 32) {
        int pi = p_sh[j];
        s += (double)cost_sh[(size_t)(pi - 1) * KMAX + (j - 1)];
    }
    #pragma unroll
    for (int o = 16; o > 0; o >>= 1) s += __shfl_down_sync(FULL, s, o);
    if (lane == 0) d_val[g] = s;
}

__global__ void __launch_bounds__(128, 1) jv_kernel(const float* __restrict__ logits,
                                                    const int* __restrict__ gt,
                                                    const int* __restrict__ types,
                                                    const void* mask) {
    __shared__ float v_sh[KMAX];
    __shared__ float u_sh[KMAX + 1];
    __shared__ int   p_sh[KMAX + 1];     // col -> row (1-based), 0 = free
    __shared__ int   way_sh[KMAX + 1];
    __shared__ int   x_sh[KMAX + 1];     // row -> col (1-based), 0 = free
    __shared__ int   imin_sh[KMAX];
    __shared__ int   s_idx[KMAX], s_tok[KMAX];
    __shared__ int   freeA[KMAX], freeB[KMAX];
    __shared__ int2  pu_sh[KMAX + 1];
    __shared__ int   nf_sh, n_sh;

    int g = blockIdx.x;
    int tid = threadIdx.x;
    int lane = tid & 31;

    // ---- fused group build: warp 0 compacts (type, mask) hits for group g ----
    if (tid < 32) {
        int b = g / TT, t = g % TT;
        int code = d_mask_code;
        int base = b * NN;
        int cnt = 0;
        for (int p0 = 0; p0 < NN; p0 += 32) {
            int pos = p0 + lane;
            bool pred = (types[base + pos] == t) && mask_at(mask, code, base + pos);
            unsigned bal = __ballot_sync(FULL, pred);
            if (pred) {
                int r = cnt + __popc(bal & ((1u << lane) - 1u));
                if (r < KMAX) {
                    s_idx[r] = pos;
                    s_tok[r] = gt[base + pos];
                }
            }
            cnt += __popc(bal);
        }
        if (lane == 0) { n_sh = min(cnt, KMAX); d_cnt[g] = min(cnt, KMAX); }
    }
    __syncthreads();

    int n = n_sh;
    if (n == 0) { if (tid == 0) d_val[g] = 0.0; return; }

    if (tid <= n) { u_sh[tid] = 0.0f; p_sh[tid] = 0; x_sh[tid] = 0; }
    __syncthreads();

    // gather cost = -logits[b, idx[i], tok[j]] directly into shared
    const float* base = logits + (size_t)(g / TT) * NN * VV;
    int nn = n * n;
    for (int e = tid; e < nn; e += 128) {
        int i = e / n, j = e - i * n;
        cost_sh[i * KMAX + j] = -__ldg(base + (size_t)s_idx[i] * VV + s_tok[j]);
    }
    __syncthreads();

    // column reduction: v[j] = min_i c[i][j], remember argmin row (1-based)
    if (tid < n) {
        float mn = cost_sh[tid]; int am = 1;
        for (int i = 1; i < n; i++) {
            float c = cost_sh[i * KMAX + tid];
            if (c < mn) { mn = c; am = i + 1; }
        }
        v_sh[tid] = mn; imin_sh[tid] = am;
    }
    __syncthreads();
    if (tid >= 32) return;                 // warp 0 only from here

    int qmax = (n + 31) >> 5;
    if (qmax == 2)
        lapjv_solve<2>(g, n, lane, u_sh, p_sh, way_sh, x_sh, imin_sh, freeA, freeB, &nf_sh, pu_sh, v_sh);
    else if (qmax == 3)
        lapjv_solve<3>(g, n, lane, u_sh, p_sh, way_sh, x_sh, imin_sh, freeA, freeB, &nf_sh, pu_sh, v_sh);
    else if (qmax <= 1)
        lapjv_solve<1>(g, n, lane, u_sh, p_sh, way_sh, x_sh, imin_sh, freeA, freeB, &nf_sh, pu_sh, v_sh);
    else
        lapjv_solve<4>(g, n, lane, u_sh, p_sh, way_sh, x_sh, imin_sh, freeA, freeB, &nf_sh, pu_sh, v_sh);
}

// ---------------- kernel 4: deterministic final reduction (1024 thr) --------
__global__ void final_kernel(float* out) {
    __shared__ double red[1024];
    __shared__ int    redc[1024];
    int t = threadIdx.x;
    const float4* l4 = (const float4*)d_lse;        // 4096 float4
    double s = 0.0;
    #pragma unroll
    for (int q = 0; q < 4; q++) {
        float4 x = l4[t + q * 1024];
        s += (double)x.x + (double)x.y + (double)x.z + (double)x.w;
    }
    int cnt = 0;
    if (t < NG) { s += d_val[t]; cnt = d_cnt[t]; }
    red[t] = s; redc[t] = cnt;
    __syncthreads();
    for (int o = 512; o > 0; o >>= 1) {
        if (t < o) { red[t] += red[t + o]; redc[t] += redc[t + o]; }
        __syncthreads();
    }
    if (t == 0) out[0] = (float)(red[0] / (double)redc[0]);
}

// ---------------- launcher ----------------
extern "C" void kernel_launch(void* const* d_in, const int* in_sizes, int n_in,
                              void* d_out, int out_size) {
    const float* logits = (const float*)d_in[0];
    const int*   gt     = (const int*)d_in[1];
    const int*   types  = (const int*)d_in[2];
    const void*  mask   = d_in[3];

    cudaFuncSetAttribute(jv_kernel, cudaFuncAttributeMaxDynamicSharedMemorySize,
                         KMAX * KMAX * (int)sizeof(float));

    // one-time side-stream setup (host objects only; no device memory)
    static int have_streams = -1;
    static cudaStream_t s2;
    static cudaEvent_t evF, evJ;
    if (have_streams < 0) {
        int lo = 0, hi = 0;
        cudaDeviceGetStreamPriorityRange(&lo, &hi);   // lo = least priority
        have_streams =
            (cudaStreamCreateWithPriority(&s2, cudaStreamNonBlocking, lo) == cudaSuccess &&
             cudaEventCreateWithFlags(&evF, cudaEventDisableTiming) == cudaSuccess &&
             cudaEventCreateWithFlags(&evJ, cudaEventDisableTiming) == cudaSuccess) ? 1 : 0;
    }

    detect_mask_kernel<<<1, 256>>>((const unsigned char*)mask);

    if (have_streams) {
        cudaEventRecord(evF, 0);                     // after detect (lse dep)
        jv_kernel<<<NG, 128, KMAX * KMAX * (int)sizeof(float)>>>(logits, gt, types, mask);
        // fork lse AFTER jv is enqueued, on a low-priority stream: jv's 128
        // blocks grab their SMs first; lse fills remaining capacity under it.
        cudaStreamWaitEvent(s2, evF, 0);
        lse_kernel<<<BB*NN, 128, 0, s2>>>(logits, mask);
        cudaEventRecord(evJ, s2);
        cudaStreamWaitEvent(0, evJ, 0);              // join before final
    } else {
        lse_kernel<<<BB*NN, 128>>>(logits, mask);
        jv_kernel<<<NG, 128, KMAX * KMAX * (int)sizeof(float)>>>(logits, gt, types, mask);
    }
    final_kernel<<<1, 1024>>>((float*)d_out);
}

// round 13
// speedup vs baseline: 1.4097x; 1.0812x over previous
#include <cuda_runtime.h>
#include <cuda_bf16.h>
#include <math.h>

// Problem shape (fixed by the dataset)
#define BB 16
#define NN 1024
#define VV 4096
#define TT 8
#define NG (BB*TT)       // 128 (batch, type) groups
#define KMAX 128         // max group size
#define CHAINCAP 8
#define FULL 0xFFFFFFFFu

// ---------------- device scratch (static; no allocations) ----------------
__device__ int    d_mask_code;          // 0=uint8, 1=int32, 2=float32
__device__ int    d_cnt[NG];
__device__ int    d_idx[NG][KMAX];
__device__ int    d_tok[NG][KMAX];
__device__ float  d_lse[BB*NN];
__device__ double d_lse_part[16];
__device__ double d_val[NG];

// ---------------- helpers ----------------
__device__ __forceinline__ bool mask_at(const void* m, int code, int i) {
    if (code == 0) return ((const unsigned char*)m)[i] != 0;
    if (code == 1) return ((const int*)m)[i] != 0;
    return ((const float*)m)[i] != 0.0f;
}

// order-preserving float -> uint key (monotone), and inverse (exact bit ops)
__device__ __forceinline__ unsigned fkey(float f) {
    unsigned b = __float_as_uint(f);
    return (b & 0x80000000u) ? ~b : (b | 0x80000000u);
}
__device__ __forceinline__ float fkey_inv(unsigned k) {
    unsigned b = (k & 0x80000000u) ? (k ^ 0x80000000u) : ~k;
    return __uint_as_float(b);
}

// ---------------- kernel 1: classify mask dtype layout ----------------
__global__ void detect_mask_kernel(const unsigned char* m) {
    __shared__ int nz[4];
    if (threadIdx.x < 4) nz[threadIdx.x] = 0;
    __syncthreads();
    int local[4] = {0,0,0,0};
    for (int i = threadIdx.x; i < BB*NN; i += blockDim.x)
        if (m[i]) local[i & 3] = 1;
    for (int c = 0; c < 4; c++) if (local[c]) atomicOr(&nz[c], 1);
    __syncthreads();
    if (threadIdx.x == 0) {
        int code;
        if (nz[1])      code = 0;  // bytes at offset%4==1 nonzero -> uint8/bool layout
        else if (nz[0]) code = 1;  // only LSB of each word -> int32 0/1
        else            code = 2;  // pattern of 1.0f (bytes 2,3) -> float32
        d_mask_code = code;
    }
}

// ---------------- kernel 2: build (b,type) groups (ordered, deterministic) ---
__global__ void group_build_kernel(const int* __restrict__ gt,
                                   const int* __restrict__ types,
                                   const void* mask) {
    int g = blockIdx.x;
    int b = g / TT, t = g % TT;
    int lane = threadIdx.x;
    int code = d_mask_code;
    int base = b * NN;
    int cnt = 0;
    for (int p0 = 0; p0 < NN; p0 += 32) {
        int pos = p0 + lane;
        bool pred = (types[base + pos] == t) && mask_at(mask, code, base + pos);
        unsigned bal = __ballot_sync(FULL, pred);
        if (pred) {
            int r = cnt + __popc(bal & ((1u << lane) - 1u));
            if (r < KMAX) {
                d_idx[g][r] = pos;
                d_tok[g][r] = gt[base + pos];
            }
        }
        cnt += __popc(bal);
    }
    if (lane == 0) d_cnt[g] = min(cnt, KMAX);
}

// ---------------- kernel 3: per-masked-row logsumexp (memory-bound bulk) ----
__global__ void lse_kernel(const float* __restrict__ logits, const void* mask) {
    int r = blockIdx.x;                     // 0 .. BB*NN-1
    if (!mask_at(mask, d_mask_code, r)) {
        if (threadIdx.x == 0) d_lse[r] = 0.0f;
        return;
    }
    const float4* row = (const float4*)(logits + (size_t)r * VV);  // 1024 float4
    int t = threadIdx.x;                    // blockDim = 128
    float4 vb[8];
    float mx = -INFINITY;
    #pragma unroll
    for (int q = 0; q < 8; q++) {
        vb[q] = row[t + q * 128];
        mx = fmaxf(mx, fmaxf(fmaxf(vb[q].x, vb[q].y), fmaxf(vb[q].z, vb[q].w)));
    }
    __shared__ float sm[4];
    #pragma unroll
    for (int o = 16; o > 0; o >>= 1) mx = fmaxf(mx, __shfl_xor_sync(FULL, mx, o));
    if ((t & 31) == 0) sm[t >> 5] = mx;
    __syncthreads();
    mx = fmaxf(fmaxf(sm[0], sm[1]), fmaxf(sm[2], sm[3]));
    float s = 0.0f;
    #pragma unroll
    for (int q = 0; q < 8; q++)
        s += __expf(vb[q].x - mx) + __expf(vb[q].y - mx)
           + __expf(vb[q].z - mx) + __expf(vb[q].w - mx);
    __shared__ float ss[4];
    #pragma unroll
    for (int o = 16; o > 0; o >>= 1) s += __shfl_xor_sync(FULL, s, o);
    if ((t & 31) == 0) ss[t >> 5] = s;
    __syncthreads();
    if (t == 0) d_lse[r] = mx + logf(ss[0] + ss[1] + ss[2] + ss[3]);
}

// ---- kernel 3b: partial lse sums (runs on side stream, hidden under jv) ----
__global__ void lse_part_kernel() {
    __shared__ double red[1024];
    int t = threadIdx.x;
    red[t] = (double)d_lse[blockIdx.x * 1024 + t];
    __syncthreads();
    for (int o = 512; o > 0; o >>= 1) {
        if (t < o) red[t] += red[t + o];
        __syncthreads();
    }
    if (t == 0) d_lse_part[blockIdx.x] = red[0];
}

// ---------------- kernel 4: fused gather + LAPJV solver (R8, protected) -----
extern __shared__ float cost_sh[];   // KMAX*KMAX floats = 64KB dynamic

// Warp-level LAPJV solver, templated on QMAX = ceil(n/32).
// Exact 2-REDUX min selection; packed (p,u) int2 shared array on the chain.
template<int QMAX>
__device__ void lapjv_solve(int g, int n, int lane,
                            float* u_sh, int* p_sh, int* way_sh, int* x_sh,
                            int* imin_sh, int* freeA, int* freeB, int* nf_shp,
                            int2* pu_sh, const float* v_init) {
    float v[QMAX];
    #pragma unroll
    for (int q = 0; q < QMAX; q++) { int j = q * 32 + lane; v[q] = (j < n) ? v_init[j] : 0.0f; }

    // greedy: assign each column to its argmin row if that row is still free
    if (lane == 0) {
        for (int j = 1; j <= n; j++) {
            int i = imin_sh[j - 1];
            if (x_sh[i] == 0) { x_sh[i] = j; p_sh[j] = i; }
        }
        int nf = 0;
        for (int i = 1; i <= n; i++) if (x_sh[i] == 0) freeA[nf++] = i;
        *nf_shp = nf;
    }
    __syncwarp();
    int nf = *nf_shp;

    // ---- chain-capped augmenting row reduction (exact keys, 2 passes) ----
    // All shared updates inside are warp-uniform values written by ALL lanes.
    int budget = 2 * n + 32;
    for (int pass = 0; pass < 2 && nf > 0 && budget > 0; pass++) {
        int* cur = (pass == 0) ? freeA : freeB;
        int* nxt = (pass == 0) ? freeB : freeA;
        int newnf = 0;
        for (int k = 0; k < nf && budget > 0; k++) {
            int i = cur[k];
            int chain = 0;
            while (i != 0 && budget > 0) {
                budget--; chain++;
                const float* crow = cost_sh + (size_t)(i - 1) * KMAX;
                unsigned kq[QMAX];
                unsigned b1 = FULL; int bj1 = 0x7FFFFFFF;
                #pragma unroll
                for (int q = 0; q < QMAX; q++) {
                    int j = q * 32 + lane + 1;
                    if (j <= n) {
                        kq[q] = fkey(crow[j - 1] - v[q]);
                        if (kq[q] < b1) { b1 = kq[q]; bj1 = j; }
                    } else kq[q] = FULL;
                }
                unsigned k1 = __reduce_min_sync(FULL, b1);
                int j1 = (int)__reduce_min_sync(FULL,
                            (b1 == k1) ? (unsigned)bj1 : 0x7FFFFFFFu);
                // second min (exclude column j1)
                unsigned b2 = FULL; int bj2 = 0x7FFFFFFF;
                #pragma unroll
                for (int q = 0; q < QMAX; q++) {
                    int j = q * 32 + lane + 1;
                    unsigned kk = (j == j1) ? FULL : kq[q];
                    if (kk < b2) { b2 = kk; bj2 = j; }
                }
                unsigned k2 = __reduce_min_sync(FULL, b2);
                int j2 = (int)__reduce_min_sync(FULL,
                            (b2 == k2) ? (unsigned)bj2 : 0x7FFFFFFFu);
                float u1 = fkey_inv(k1), u2 = fkey_inv(k2);
                bool strict = (u1 < u2);

                int jt = j1;
                int i1 = p_sh[jt];              // uniform broadcast read
                if (!strict && i1 != 0) { jt = j2; i1 = p_sh[jt]; }
                if (strict) {
                    int ol = (j1 - 1) & 31, oq = (j1 - 1) >> 5;
                    if (lane == ol) {
                        #pragma unroll
                        for (int q = 0; q < QMAX; q++) if (q == oq) v[q] -= (u2 - u1);
                    }
                }
                // uniform all-lane writes (same value -> benign, self-visible)
                x_sh[i] = jt; p_sh[jt] = i; u_sh[i] = u2;
                if (i1 != 0) x_sh[i1] = 0;
                if (i1 != 0) {
                    if (strict && chain < CHAINCAP) {
                        i = i1;                  // continue chain with displaced row
                    } else {
                        nxt[newnf] = i1; newnf++; i = 0;
                    }
                } else i = 0;
            }
            if (i != 0) { nxt[newnf] = i; newnf++; }   // budget exhausted mid-chain
        }
        __syncwarp();
        nf = newnf;
    }

    // ---- build freelist of remaining free rows + packed pu array ----
    if (lane == 0) {
        int c = 0;
        for (int i = 1; i <= n; i++) if (x_sh[i] == 0) freeA[c++] = i;
        *nf_shp = c;
    }
    for (int j = lane + 1; j <= n; j += 32) {
        int pi = p_sh[j];
        pu_sh[j] = make_int2(pi, pi ? __float_as_int(u_sh[pi]) : 0);
    }
    __syncwarp();
    int nfree = *nf_shp;

    // ---- Dijkstra rounds (absolute-distance, exact 2-REDUX, pu-packed) ----
    for (int fi = 0; fi < nfree; fi++) {
        int i = freeA[fi];
        float    dist[QMAX];
        unsigned bkey[QMAX];
        unsigned usedm = 0;
        #pragma unroll
        for (int q = 0; q < QMAX; q++) { dist[q] = INFINITY; bkey[q] = FULL; }

        float D = 0.0f;
        float ui0 = u_sh[i];                    // once per round
        int j0 = 0, i0 = i;
        while (true) {
            const float* crow = cost_sh + (size_t)(i0 - 1) * KMAX;
            float bse = D - ui0;
            #pragma unroll
            for (int q = 0; q < QMAX; q++) {
                int j = q * 32 + lane + 1;
                if (j <= n && !((usedm >> q) & 1u)) {
                    float cur = crow[j - 1] + (bse - v[q]);
                    if (cur < dist[q]) { dist[q] = cur; bkey[q] = fkey(cur); way_sh[j] = j0; }
                }
            }
            unsigned bk = bkey[0]; int bq = 0;
            #pragma unroll
            for (int q = 1; q < QMAX; q++) if (bkey[q] < bk) { bk = bkey[q]; bq = q; }
            unsigned kmin = __reduce_min_sync(FULL, bk);
            int jc = (bk == kmin) ? (bq * 32 + lane + 1) : 0x7FFFFFFF;
            int j1 = (int)__reduce_min_sync(FULL, (unsigned)jc);
            D = fkey_inv(kmin);                 // exact settled distance

            int2 pu = pu_sh[j1];                // single LDS.64: row + its u
            j0 = j1;
            if (pu.x == 0) break;               // reached a free column
            int ol = (j1 - 1) & 31, oq = (j1 - 1) >> 5;
            if (lane == ol) {
                usedm |= (1u << oq);
                #pragma unroll
                for (int q = 0; q < QMAX; q++) if (q == oq) bkey[q] = FULL;
            }
            i0 = pu.x; ui0 = __int_as_float(pu.y);
        }

        // end-of-round potential updates
        if (lane == 0) u_sh[i] += D;
        #pragma unroll
        for (int q = 0; q < QMAX; q++) {
            if ((usedm >> q) & 1u) {
                int j = q * 32 + lane + 1;
                float incr = D - dist[q];
                v[q] -= incr;
                u_sh[p_sh[j]] += incr;          // distinct rows, no conflict
            }
        }
        __syncwarp();                           // publish way_sh/u_sh
        if (lane == 0) {
            p_sh[0] = i;                        // root for augmentation
            int j = j0;
            while (j) { int jp = way_sh[j]; p_sh[j] = p_sh[jp]; j = jp; }
        }
        __syncwarp();                           // publish p_sh
        // rebuild packed pu (u and p changed for used/path columns)
        for (int j = lane + 1; j <= n; j += 32) {
            int pi = p_sh[j];
            pu_sh[j] = make_int2(pi, pi ? __float_as_int(u_sh[pi]) : 0);
        }
        __syncwarp();
    }

    // optimal value = sum_j cost[p[j]-1][j-1]
    double s = 0.0;
    for (int j = lane + 1; j <= n; j += 32) {
        int pi = p_sh[j];
        s += (double)cost_sh[(size_t)(pi - 1) * KMAX + (j - 1)];
    }
    #pragma unroll
    for (int o = 16; o > 0; o >>= 1) s += __shfl_down_sync(FULL, s, o);
    if (lane == 0) d_val[g] = s;
}

__global__ void __launch_bounds__(128, 1) jv_kernel(const float* __restrict__ logits) {
    __shared__ float v_sh[KMAX];
    __shared__ float u_sh[KMAX + 1];
    __shared__ int   p_sh[KMAX + 1];     // col -> row (1-based), 0 = free
    __shared__ int   way_sh[KMAX + 1];
    __shared__ int   x_sh[KMAX + 1];     // row -> col (1-based), 0 = free
    __shared__ int   imin_sh[KMAX];
    __shared__ int   s_idx[KMAX], s_tok[KMAX];
    __shared__ int   freeA[KMAX], freeB[KMAX];
    __shared__ int2  pu_sh[KMAX + 1];
    __shared__ int   nf_sh;

    int g = blockIdx.x;
    int n = d_cnt[g];
    int tid = threadIdx.x;
    if (n == 0) { if (tid == 0) d_val[g] = 0.0; return; }

    if (tid < n) { s_idx[tid] = d_idx[g][tid]; s_tok[tid] = d_tok[g][tid]; }
    if (tid <= n) { u_sh[tid] = 0.0f; p_sh[tid] = 0; x_sh[tid] = 0; }
    __syncthreads();

    // gather cost = -logits[b, idx[i], tok[j]] directly into shared
    const float* base = logits + (size_t)(g / TT) * NN * VV;
    int nn = n * n;
    for (int e = tid; e < nn; e += 128) {
        int i = e / n, j = e - i * n;
        cost_sh[i * KMAX + j] = -__ldg(base + (size_t)s_idx[i] * VV + s_tok[j]);
    }
    __syncthreads();

    // column reduction: v[j] = min_i c[i][j], remember argmin row (1-based)
    if (tid < n) {
        float mn = cost_sh[tid]; int am = 1;
        for (int i = 1; i < n; i++) {
            float c = cost_sh[i * KMAX + tid];
            if (c < mn) { mn = c; am = i + 1; }
        }
        v_sh[tid] = mn; imin_sh[tid] = am;
    }
    __syncthreads();
    if (tid >= 32) return;                 // warp 0 only from here
    int lane = tid;

    int qmax = (n + 31) >> 5;
    if (qmax == 2)
        lapjv_solve<2>(g, n, lane, u_sh, p_sh, way_sh, x_sh, imin_sh, freeA, freeB, &nf_sh, pu_sh, v_sh);
    else if (qmax == 3)
        lapjv_solve<3>(g, n, lane, u_sh, p_sh, way_sh, x_sh, imin_sh, freeA, freeB, &nf_sh, pu_sh, v_sh);
    else if (qmax <= 1)
        lapjv_solve<1>(g, n, lane, u_sh, p_sh, way_sh, x_sh, imin_sh, freeA, freeB, &nf_sh, pu_sh, v_sh);
    else
        lapjv_solve<4>(g, n, lane, u_sh, p_sh, way_sh, x_sh, imin_sh, freeA, freeB, &nf_sh, pu_sh, v_sh);
}

// ---------------- kernel 5: tiny deterministic final reduction --------------
__global__ void final_kernel(float* out) {
    __shared__ double red[128];
    __shared__ int    redc[128];
    int t = threadIdx.x;                           // blockDim = 128
    double s = d_val[t];
    int cnt = d_cnt[t];
    if (t < 16) s += d_lse_part[t];
    red[t] = s; redc[t] = cnt;
    __syncthreads();
    for (int o = 64; o > 0; o >>= 1) {
        if (t < o) { red[t] += red[t + o]; redc[t] += redc[t + o]; }
        __syncthreads();
    }
    if (t == 0) out[0] = (float)(red[0] / (double)redc[0]);
}

// ---------------- launcher ----------------
extern "C" void kernel_launch(void* const* d_in, const int* in_sizes, int n_in,
                              void* d_out, int out_size) {
    const float* logits = (const float*)d_in[0];
    const int*   gt     = (const int*)d_in[1];
    const int*   types  = (const int*)d_in[2];
    const void*  mask   = d_in[3];

    cudaFuncSetAttribute(jv_kernel, cudaFuncAttributeMaxDynamicSharedMemorySize,
                         KMAX * KMAX * (int)sizeof(float));

    // one-time side-stream setup (host objects only; no device memory)
    static int have_streams = -1;
    static cudaStream_t s2;
    static cudaEvent_t evF, evJ;
    if (have_streams < 0) {
        int lo = 0, hi = 0;
        cudaDeviceGetStreamPriorityRange(&lo, &hi);   // lo = least priority
        have_streams =
            (cudaStreamCreateWithPriority(&s2, cudaStreamNonBlocking, lo) == cudaSuccess &&
             cudaEventCreateWithFlags(&evF, cudaEventDisableTiming) == cudaSuccess &&
             cudaEventCreateWithFlags(&evJ, cudaEventDisableTiming) == cudaSuccess) ? 1 : 0;
    }

    detect_mask_kernel<<<1, 256>>>((const unsigned char*)mask);

    if (have_streams) {
        cudaEventRecord(evF, 0);                     // after detect (lse dep)
        group_build_kernel<<<NG, 32>>>(gt, types, mask);
        jv_kernel<<<NG, 128, KMAX * KMAX * (int)sizeof(float)>>>(logits);
        // fork lse AFTER jv is enqueued, on a low-priority stream: jv's 128
        // blocks grab their SMs first; lse + its partial sum hide under jv.
        cudaStreamWaitEvent(s2, evF, 0);
        lse_kernel<<<BB*NN, 128, 0, s2>>>(logits, mask);
        lse_part_kernel<<<16, 1024, 0, s2>>>();
        cudaEventRecord(evJ, s2);
        cudaStreamWaitEvent(0, evJ, 0);              // join before final
    } else {
        lse_kernel<<<BB*NN, 128>>>(logits, mask);
        lse_part_kernel<<<16, 1024>>>();
        group_build_kernel<<<NG, 32>>>(gt, types, mask);
        jv_kernel<<<NG, 128, KMAX * KMAX * (int)sizeof(float)>>>(logits);
    }
    final_kernel<<<1, 128>>>((float*)d_out);
}